// round 1
// baseline (speedup 1.0000x reference)
#include <cuda_runtime.h>
#include <math.h>

#define BD   2
#define SD   2048
#define DD   1024
#define HH   16
#define DHH  64
#define FFD  4096
#define NR   (BD*SD)              // 4096 rows
#define NEGV (-1000000000.0f)

// ---------------- scratch (static device globals; no allocation allowed) ----
__device__ float g_x  [NR*DD];            // residual stream (post-LN1)
__device__ float g_q  [NR*DD];
__device__ float g_k  [NR*DD];
__device__ float g_v  [NR*DD];
__device__ float g_att[NR*DD];            // attention output (head-concat)
__device__ float g_ao [NR*DD];            // attn @ Wo + bo
__device__ float g_xn [NR*DD];            // LN3(x)
__device__ float g_h  [(size_t)NR*FFD];   // FFN hidden (64 MB)
__device__ float g_pad[NR];               // key pad mask additive (-1e9 / 0)

// ---------------- block-wide sum over 256 threads ---------------------------
__device__ __forceinline__ float blockSum(float v, float* sm) {
    int lane = threadIdx.x & 31;
    #pragma unroll
    for (int o = 16; o; o >>= 1) v += __shfl_xor_sync(0xffffffffu, v, o);
    if (lane == 0) sm[threadIdx.x >> 5] = v;
    __syncthreads();
    float t = sm[lane & 7];
    #pragma unroll
    for (int o = 4; o; o >>= 1) t += __shfl_xor_sync(0xffffffffu, t, o);
    __syncthreads();
    return t;
}

// ---------------- K1: embedding + pos + LN1 -> g_x ; pad mask ---------------
__global__ void embed_ln_k(const int* __restrict__ tok,
                           const float* __restrict__ emb,
                           const float* __restrict__ pos,
                           const float* __restrict__ gam,
                           const float* __restrict__ bet) {
    __shared__ float sm[8];
    int n = blockIdx.x;
    int t = tok[n];
    int s = n & (SD - 1);
    int c0 = threadIdx.x * 4;
    float4 e = *(const float4*)(emb + (size_t)t * DD + c0);
    float4 p = *(const float4*)(pos + (size_t)s * DD + c0);
    float v0 = e.x + p.x, v1 = e.y + p.y, v2 = e.z + p.z, v3 = e.w + p.w;
    float mean = blockSum(v0 + v1 + v2 + v3, sm) * (1.0f / DD);
    float d0 = v0 - mean, d1 = v1 - mean, d2 = v2 - mean, d3 = v3 - mean;
    float var = blockSum(d0*d0 + d1*d1 + d2*d2 + d3*d3, sm) * (1.0f / DD);
    float rs = rsqrtf(var + 1e-5f);
    float4 gg = *(const float4*)(gam + c0);
    float4 bb = *(const float4*)(bet + c0);
    float4 o;
    o.x = d0 * rs * gg.x + bb.x;
    o.y = d1 * rs * gg.y + bb.y;
    o.z = d2 * rs * gg.z + bb.z;
    o.w = d3 * rs * gg.w + bb.w;
    *(float4*)(g_x + (size_t)n * DD + c0) = o;
    if (threadIdx.x == 0) g_pad[n] = (t == 0) ? NEGV : 0.0f;
}

// ---------------- LN kernels: MODE 0: g_x += LN(in); MODE 1: g_xn = LN(in) --
template <int MODE>
__global__ void ln_k(const float* __restrict__ in,
                     const float* __restrict__ gam,
                     const float* __restrict__ bet) {
    __shared__ float sm[8];
    int n = blockIdx.x;
    int c0 = threadIdx.x * 4;
    float4 iv = *(const float4*)(in + (size_t)n * DD + c0);
    float mean = blockSum(iv.x + iv.y + iv.z + iv.w, sm) * (1.0f / DD);
    float d0 = iv.x - mean, d1 = iv.y - mean, d2 = iv.z - mean, d3 = iv.w - mean;
    float var = blockSum(d0*d0 + d1*d1 + d2*d2 + d3*d3, sm) * (1.0f / DD);
    float rs = rsqrtf(var + 1e-5f);
    float4 gg = *(const float4*)(gam + c0);
    float4 bb = *(const float4*)(bet + c0);
    float4 o;
    o.x = d0 * rs * gg.x + bb.x;
    o.y = d1 * rs * gg.y + bb.y;
    o.z = d2 * rs * gg.z + bb.z;
    o.w = d3 * rs * gg.w + bb.w;
    if (MODE == 0) {
        float4 x = *(float4*)(g_x + (size_t)n * DD + c0);
        x.x += o.x; x.y += o.y; x.z += o.z; x.w += o.w;
        *(float4*)(g_x + (size_t)n * DD + c0) = x;
    } else {
        *(float4*)(g_xn + (size_t)n * DD + c0) = o;
    }
}

// ---------------- generic fp32 GEMM: C[N,M] = A[N,K] @ W[K,M] + bias --------
// EPI 0: + bias     EPI 1: gelu(+bias)     EPI 2: + bias + res
__device__ __forceinline__ float gelu_f(float x) {
    return 0.5f * x * (1.0f + erff(x * 0.70710678118654752f));
}

template <int EPI>
__global__ __launch_bounds__(256, 2)
void gemm128(const float* __restrict__ A, const float* __restrict__ W,
             const float* __restrict__ bias, float* __restrict__ C,
             int K, int M, const float* __restrict__ res) {
    __shared__ float As[8][128];
    __shared__ float Bs[8][128];
    int tid = threadIdx.x;
    int bx = blockIdx.x, by = blockIdx.y;

    int arow = tid >> 1;              // 0..127
    int ak4  = (tid & 1) * 4;         // 0 / 4
    int bk   = tid >> 5;              // 0..7
    int bc   = (tid & 31) * 4;        // 0..124

    const float* Aptr = A + (size_t)(by * 128 + arow) * K + ak4;
    const float* Bptr = W + (size_t)bk * M + bx * 128 + bc;

    int utr = (tid >> 4) * 8;         // 0..120
    int utc = (tid & 15) * 8;

    float acc[8][8];
    #pragma unroll
    for (int i = 0; i < 8; i++)
        #pragma unroll
        for (int j = 0; j < 8; j++) acc[i][j] = 0.0f;

    for (int k0 = 0; k0 < K; k0 += 8) {
        float4 a = *(const float4*)(Aptr + k0);
        As[ak4 + 0][arow] = a.x;
        As[ak4 + 1][arow] = a.y;
        As[ak4 + 2][arow] = a.z;
        As[ak4 + 3][arow] = a.w;
        *(float4*)&Bs[bk][bc] = *(const float4*)(Bptr + (size_t)k0 * M);
        __syncthreads();
        #pragma unroll
        for (int k = 0; k < 8; k++) {
            float ar[8], br[8];
            *(float4*)(ar)     = *(float4*)&As[k][utr];
            *(float4*)(ar + 4) = *(float4*)&As[k][utr + 4];
            *(float4*)(br)     = *(float4*)&Bs[k][utc];
            *(float4*)(br + 4) = *(float4*)&Bs[k][utc + 4];
            #pragma unroll
            for (int i = 0; i < 8; i++)
                #pragma unroll
                for (int j = 0; j < 8; j++)
                    acc[i][j] += ar[i] * br[j];
        }
        __syncthreads();
    }

    #pragma unroll
    for (int i = 0; i < 8; i++) {
        size_t roff = (size_t)(by * 128 + utr + i) * M + bx * 128 + utc;
        #pragma unroll
        for (int j4 = 0; j4 < 8; j4 += 4) {
            float4 o;
            float b0 = bias[bx * 128 + utc + j4 + 0];
            float b1 = bias[bx * 128 + utc + j4 + 1];
            float b2 = bias[bx * 128 + utc + j4 + 2];
            float b3 = bias[bx * 128 + utc + j4 + 3];
            o.x = acc[i][j4 + 0] + b0;
            o.y = acc[i][j4 + 1] + b1;
            o.z = acc[i][j4 + 2] + b2;
            o.w = acc[i][j4 + 3] + b3;
            if (EPI == 1) {
                o.x = gelu_f(o.x); o.y = gelu_f(o.y);
                o.z = gelu_f(o.z); o.w = gelu_f(o.w);
            }
            if (EPI == 2) {
                float4 r = *(const float4*)(res + roff + j4);
                o.x += r.x; o.y += r.y; o.z += r.z; o.w += r.w;
            }
            *(float4*)(C + roff + j4) = o;
        }
    }
}

// ---------------- fused flash attention (fp32, causal + pad mask) -----------
// grid: (qtile=32, bh=32), 256 threads. 64 queries per block, key blocks of 64.
__global__ __launch_bounds__(256, 2)
void attn_k() {
    __shared__ float Qs[64][64];
    __shared__ float KP[64][64];   // K^T during S-compute, then reused for P
    __shared__ float Vs[64][64];

    int qt = blockIdx.x, bh = blockIdx.y;
    int b = bh >> 4, h = bh & 15;
    int tid = threadIdx.x;
    int ty = tid >> 4, tx = tid & 15;
    int lr = tid >> 2;              // load row 0..63
    int ld0 = (tid & 3) * 16;       // load col start (16 floats per thread)

    // load Q tile
    {
        size_t qb = (size_t)(b * SD + qt * 64 + lr) * DD + h * DHH + ld0;
        #pragma unroll
        for (int q = 0; q < 4; q++)
            *(float4*)&Qs[lr][ld0 + q * 4] = *(const float4*)(g_q + qb + q * 4);
    }

    float Oa[4][4];
    float m[4], l[4];
    #pragma unroll
    for (int i = 0; i < 4; i++) {
        m[i] = -1e30f; l[i] = 0.0f;
        #pragma unroll
        for (int j = 0; j < 4; j++) Oa[i][j] = 0.0f;
    }
    const float scale = 0.125f;

    for (int kb = 0; kb <= qt; kb++) {
        __syncthreads();   // Q visible (iter 0); prior KP/Vs reads complete
        // load K (transposed) and V tiles
        {
            size_t kbse = (size_t)(b * SD + kb * 64 + lr) * DD + h * DHH + ld0;
            #pragma unroll
            for (int q = 0; q < 4; q++) {
                float4 kv = *(const float4*)(g_k + kbse + q * 4);
                KP[ld0 + q * 4 + 0][lr] = kv.x;
                KP[ld0 + q * 4 + 1][lr] = kv.y;
                KP[ld0 + q * 4 + 2][lr] = kv.z;
                KP[ld0 + q * 4 + 3][lr] = kv.w;
                *(float4*)&Vs[lr][ld0 + q * 4] = *(const float4*)(g_v + kbse + q * 4);
            }
        }
        __syncthreads();

        // S = Q K^T  (each thread: rows ty*4+i, cols tx*4+j)
        float sv[4][4];
        #pragma unroll
        for (int i = 0; i < 4; i++)
            #pragma unroll
            for (int j = 0; j < 4; j++) sv[i][j] = 0.0f;

        #pragma unroll
        for (int d = 0; d < 64; d += 4) {
            float kr[4][4];
            #pragma unroll
            for (int dd = 0; dd < 4; dd++) {
                float4 t = *(float4*)&KP[d + dd][tx * 4];
                kr[dd][0] = t.x; kr[dd][1] = t.y; kr[dd][2] = t.z; kr[dd][3] = t.w;
            }
            #pragma unroll
            for (int i = 0; i < 4; i++) {
                float4 q4 = *(float4*)&Qs[ty * 4 + i][d];
                float qa[4] = {q4.x, q4.y, q4.z, q4.w};
                #pragma unroll
                for (int dd = 0; dd < 4; dd++)
                    #pragma unroll
                    for (int j = 0; j < 4; j++)
                        sv[i][j] += qa[dd] * kr[dd][j];
            }
        }

        // masks + online softmax
        float4 pd = *(const float4*)(g_pad + (size_t)b * SD + kb * 64 + tx * 4);
        float padv[4] = {pd.x, pd.y, pd.z, pd.w};
        bool diag = (kb == qt);
        float p[4][4];
        #pragma unroll
        for (int i = 0; i < 4; i++) {
            int qrow = ty * 4 + i;
            float mx = -1e30f;
            #pragma unroll
            for (int j = 0; j < 4; j++) {
                float val = sv[i][j] * scale + padv[j];
                if (diag && (tx * 4 + j) > qrow) val += NEGV;
                sv[i][j] = val;
                mx = fmaxf(mx, val);
            }
            #pragma unroll
            for (int o = 8; o; o >>= 1)
                mx = fmaxf(mx, __shfl_xor_sync(0xffffffffu, mx, o));
            float mn = fmaxf(m[i], mx);
            float corr = __expf(m[i] - mn);
            m[i] = mn;
            float rs = 0.0f;
            #pragma unroll
            for (int j = 0; j < 4; j++) {
                p[i][j] = __expf(sv[i][j] - mn);
                rs += p[i][j];
            }
            #pragma unroll
            for (int o = 8; o; o >>= 1)
                rs += __shfl_xor_sync(0xffffffffu, rs, o);
            l[i] = l[i] * corr + rs;
            #pragma unroll
            for (int j = 0; j < 4; j++) Oa[i][j] *= corr;
        }

        __syncthreads();   // all KP reads done -> safe to overwrite with P
        #pragma unroll
        for (int i = 0; i < 4; i++) {
            float4 o = make_float4(p[i][0], p[i][1], p[i][2], p[i][3]);
            *(float4*)&KP[ty * 4 + i][tx * 4] = o;
        }
        __syncthreads();

        // O += P @ V
        #pragma unroll
        for (int k = 0; k < 64; k += 4) {
            float vr[4][4];
            #pragma unroll
            for (int kk = 0; kk < 4; kk++) {
                float4 t = *(float4*)&Vs[k + kk][tx * 4];
                vr[kk][0] = t.x; vr[kk][1] = t.y; vr[kk][2] = t.z; vr[kk][3] = t.w;
            }
            #pragma unroll
            for (int i = 0; i < 4; i++) {
                float4 pr = *(float4*)&KP[ty * 4 + i][k];
                float pa[4] = {pr.x, pr.y, pr.z, pr.w};
                #pragma unroll
                for (int kk = 0; kk < 4; kk++)
                    #pragma unroll
                    for (int j = 0; j < 4; j++)
                        Oa[i][j] += pa[kk] * vr[kk][j];
            }
        }
    }

    // write normalized output (head-concat layout [N, 1024])
    #pragma unroll
    for (int i = 0; i < 4; i++) {
        float inv = 1.0f / l[i];
        size_t off = (size_t)(b * SD + qt * 64 + ty * 4 + i) * DD + h * DHH + tx * 4;
        float4 o = make_float4(Oa[i][0] * inv, Oa[i][1] * inv,
                               Oa[i][2] * inv, Oa[i][3] * inv);
        *(float4*)(g_att + off) = o;
    }
}

// ---------------- launch --------------------------------------------------
extern "C" void kernel_launch(void* const* d_in, const int* in_sizes, int n_in,
                              void* d_out, int out_size) {
    const int*   tokens = (const int*)  d_in[0];
    const float* emb    = (const float*)d_in[1];
    const float* pos    = (const float*)d_in[2];
    const float* ln1_g  = (const float*)d_in[3];
    const float* ln1_b  = (const float*)d_in[4];
    const float* ln2_g  = (const float*)d_in[5];
    const float* ln2_b  = (const float*)d_in[6];
    const float* ln3_g  = (const float*)d_in[7];
    const float* ln3_b  = (const float*)d_in[8];
    const float* Wq     = (const float*)d_in[9];
    const float* bq     = (const float*)d_in[10];
    const float* Wk     = (const float*)d_in[11];
    const float* bk     = (const float*)d_in[12];
    const float* Wv     = (const float*)d_in[13];
    const float* bv     = (const float*)d_in[14];
    const float* Wo     = (const float*)d_in[15];
    const float* bo     = (const float*)d_in[16];
    const float* W1     = (const float*)d_in[17];
    const float* b1     = (const float*)d_in[18];
    const float* W2     = (const float*)d_in[19];
    const float* b2     = (const float*)d_in[20];
    float* out = (float*)d_out;

    float *xp, *qp, *kp, *vp, *attp, *aop, *xnp, *hp;
    cudaGetSymbolAddress((void**)&xp,   g_x);
    cudaGetSymbolAddress((void**)&qp,   g_q);
    cudaGetSymbolAddress((void**)&kp,   g_k);
    cudaGetSymbolAddress((void**)&vp,   g_v);
    cudaGetSymbolAddress((void**)&attp, g_att);
    cudaGetSymbolAddress((void**)&aop,  g_ao);
    cudaGetSymbolAddress((void**)&xnp,  g_xn);
    cudaGetSymbolAddress((void**)&hp,   g_h);

    // 1) embedding + pos + LN1 -> g_x ; pad mask
    embed_ln_k<<<NR, 256>>>(tokens, emb, pos, ln1_g, ln1_b);

    // 2) QKV projections
    gemm128<0><<<dim3(DD / 128, NR / 128), 256>>>(xp, Wq, bq, qp, DD, DD, nullptr);
    gemm128<0><<<dim3(DD / 128, NR / 128), 256>>>(xp, Wk, bk, kp, DD, DD, nullptr);
    gemm128<0><<<dim3(DD / 128, NR / 128), 256>>>(xp, Wv, bv, vp, DD, DD, nullptr);

    // 3) fused attention
    attn_k<<<dim3(SD / 64, BD * HH), 256>>>();

    // 4) output projection + residual LN2
    gemm128<0><<<dim3(DD / 128, NR / 128), 256>>>(attp, Wo, bo, aop, DD, DD, nullptr);
    ln_k<0><<<NR, 256>>>(aop, ln2_g, ln2_b);       // g_x += LN2(g_ao)

    // 5) FFN
    ln_k<1><<<NR, 256>>>(xp, ln3_g, ln3_b);        // g_xn = LN3(g_x)
    gemm128<1><<<dim3(FFD / 128, NR / 128), 256>>>(xnp, W1, b1, hp, DD, FFD, nullptr);
    gemm128<2><<<dim3(DD / 128, NR / 128), 256>>>(hp, W2, b2, out, FFD, DD, xp);
}

// round 3
// speedup vs baseline: 1.8573x; 1.8573x over previous
#include <cuda_runtime.h>
#include <cstdint>
#include <math.h>

#define BD   2
#define SD   2048
#define DD   1024
#define HH   16
#define DHH  64
#define FFD  4096
#define NR   (BD*SD)              // 4096 rows
#define NEGV (-1000000000.0f)

// ---------------- scratch (static device globals; no allocation allowed) ----
__device__ float g_x  [NR*DD];            // residual stream (post-LN1)
__device__ float g_q  [NR*DD];
__device__ float g_k  [NR*DD];
__device__ float g_v  [NR*DD];
__device__ float g_att[NR*DD];            // attention output (head-concat)
__device__ float g_ao [NR*DD];            // attn @ Wo + bo
__device__ float g_xn [NR*DD];            // LN3(x)
__device__ float g_h  [(size_t)NR*FFD];   // FFN hidden (64 MB)
__device__ float g_pad[NR];               // key pad mask additive (-1e9 / 0)
// transposed weights [N,K] K-major
__device__ float g_wq[DD*DD];
__device__ float g_wk[DD*DD];
__device__ float g_wv[DD*DD];
__device__ float g_wo[DD*DD];
__device__ float g_w1[(size_t)DD*FFD];
__device__ float g_w2[(size_t)DD*FFD];

// ---------------- block-wide sum over 256 threads ---------------------------
__device__ __forceinline__ float blockSum(float v, float* sm) {
    int lane = threadIdx.x & 31;
    #pragma unroll
    for (int o = 16; o; o >>= 1) v += __shfl_xor_sync(0xffffffffu, v, o);
    if (lane == 0) sm[threadIdx.x >> 5] = v;
    __syncthreads();
    float t = sm[lane & 7];
    #pragma unroll
    for (int o = 4; o; o >>= 1) t += __shfl_xor_sync(0xffffffffu, t, o);
    __syncthreads();
    return t;
}

// ---------------- K1: embedding + pos + LN1 -> g_x ; pad mask ---------------
__global__ void embed_ln_k(const int* __restrict__ tok,
                           const float* __restrict__ emb,
                           const float* __restrict__ pos,
                           const float* __restrict__ gam,
                           const float* __restrict__ bet) {
    __shared__ float sm[8];
    int n = blockIdx.x;
    int t = tok[n];
    int s = n & (SD - 1);
    int c0 = threadIdx.x * 4;
    float4 e = *(const float4*)(emb + (size_t)t * DD + c0);
    float4 p = *(const float4*)(pos + (size_t)s * DD + c0);
    float v0 = e.x + p.x, v1 = e.y + p.y, v2 = e.z + p.z, v3 = e.w + p.w;
    float mean = blockSum(v0 + v1 + v2 + v3, sm) * (1.0f / DD);
    float d0 = v0 - mean, d1 = v1 - mean, d2 = v2 - mean, d3 = v3 - mean;
    float var = blockSum(d0*d0 + d1*d1 + d2*d2 + d3*d3, sm) * (1.0f / DD);
    float rs = rsqrtf(var + 1e-5f);
    float4 gg = *(const float4*)(gam + c0);
    float4 bb = *(const float4*)(bet + c0);
    float4 o;
    o.x = d0 * rs * gg.x + bb.x;
    o.y = d1 * rs * gg.y + bb.y;
    o.z = d2 * rs * gg.z + bb.z;
    o.w = d3 * rs * gg.w + bb.w;
    *(float4*)(g_x + (size_t)n * DD + c0) = o;
    if (threadIdx.x == 0) g_pad[n] = (t == 0) ? NEGV : 0.0f;
}

// ---------------- LN kernels: MODE 0: g_x += LN(in); MODE 1: g_xn = LN(in) --
template <int MODE>
__global__ void ln_k(const float* __restrict__ in,
                     const float* __restrict__ gam,
                     const float* __restrict__ bet) {
    __shared__ float sm[8];
    int n = blockIdx.x;
    int c0 = threadIdx.x * 4;
    float4 iv = *(const float4*)(in + (size_t)n * DD + c0);
    float mean = blockSum(iv.x + iv.y + iv.z + iv.w, sm) * (1.0f / DD);
    float d0 = iv.x - mean, d1 = iv.y - mean, d2 = iv.z - mean, d3 = iv.w - mean;
    float var = blockSum(d0*d0 + d1*d1 + d2*d2 + d3*d3, sm) * (1.0f / DD);
    float rs = rsqrtf(var + 1e-5f);
    float4 gg = *(const float4*)(gam + c0);
    float4 bb = *(const float4*)(bet + c0);
    float4 o;
    o.x = d0 * rs * gg.x + bb.x;
    o.y = d1 * rs * gg.y + bb.y;
    o.z = d2 * rs * gg.z + bb.z;
    o.w = d3 * rs * gg.w + bb.w;
    if (MODE == 0) {
        float4 x = *(float4*)(g_x + (size_t)n * DD + c0);
        x.x += o.x; x.y += o.y; x.z += o.z; x.w += o.w;
        *(float4*)(g_x + (size_t)n * DD + c0) = x;
    } else {
        *(float4*)(g_xn + (size_t)n * DD + c0) = o;
    }
}

// ---------------- weight transpose: out[C,R] = in[R,C]^T --------------------
__global__ void transpose_k(const float* __restrict__ in, float* __restrict__ out,
                            int R, int Cc) {
    __shared__ float t[32][33];
    int bx = blockIdx.x * 32, by = blockIdx.y * 32;
    int x = bx + threadIdx.x;
    #pragma unroll
    for (int i = 0; i < 4; i++)
        t[threadIdx.y + i * 8][threadIdx.x] = in[(size_t)(by + threadIdx.y + i * 8) * Cc + x];
    __syncthreads();
    int xo = by + threadIdx.x;
    #pragma unroll
    for (int i = 0; i < 4; i++)
        out[(size_t)(bx + threadIdx.y + i * 8) * R + xo] = t[threadIdx.x][threadIdx.y + i * 8];
}

// ---------------- mma.sync tf32 GEMM ---------------------------------------
// C[4096,Mout] = A[4096,K] @ Bt[Mout,K]^T  (+bias / gelu / +res)
// CTA tile 128x128, 8 warps (4x2), warp tile 32x64, K-chunk 32.
__device__ __forceinline__ float gelu_f(float x) {
    return 0.5f * x * (1.0f + erff(x * 0.70710678118654752f));
}
__device__ __forceinline__ uint32_t f2tf32(float x) {
    uint32_t t;
    asm("cvt.rna.tf32.f32 %0, %1;" : "=r"(t) : "f"(x));
    return t;
}
__device__ __forceinline__ void mma1688(float* c, const uint32_t* a, const uint32_t* b) {
    asm volatile(
        "mma.sync.aligned.m16n8k8.row.col.f32.tf32.tf32.f32 "
        "{%0,%1,%2,%3}, {%4,%5,%6,%7}, {%8,%9}, {%0,%1,%2,%3};"
        : "+f"(c[0]), "+f"(c[1]), "+f"(c[2]), "+f"(c[3])
        : "r"(a[0]), "r"(a[1]), "r"(a[2]), "r"(a[3]), "r"(b[0]), "r"(b[1]));
}

#define SSTR 36   // smem row stride (floats): bank = 4*row + col -> conflict-free frags

template <int EPI>
__global__ __launch_bounds__(256)
void tc_gemm(const float* __restrict__ A, const float* __restrict__ Bt,
             const float* __restrict__ bias, float* __restrict__ C,
             int K, int Mout, const float* __restrict__ res) {
    __shared__ uint32_t sA[128 * SSTR];
    __shared__ uint32_t sB[128 * SSTR];

    int tid  = threadIdx.x;
    int wid  = tid >> 5;
    int lane = tid & 31;
    int wm   = wid >> 1;          // 0..3 -> rows wm*32
    int wn   = wid & 1;           // 0..1 -> cols wn*64
    int gq   = lane >> 2;         // group id 0..7
    int tg   = lane & 3;          // thread-in-group 0..3

    // global->smem mapping: 2 threads per row, 16 floats each
    int r  = tid >> 1;
    int cb = (tid & 1) * 16;
    const float* ArowP = A  + (size_t)(blockIdx.y * 128 + r) * K + cb;
    const float* BrowP = Bt + (size_t)(blockIdx.x * 128 + r) * K + cb;
    uint32_t* sAw = sA + r * SSTR + cb;
    uint32_t* sBw = sB + r * SSTR + cb;

    float acc[2][8][4];
    #pragma unroll
    for (int mt = 0; mt < 2; mt++)
        #pragma unroll
        for (int nt = 0; nt < 8; nt++)
            #pragma unroll
            for (int c = 0; c < 4; c++) acc[mt][nt][c] = 0.0f;

    int NC = K >> 5;
    float4 pa[4], pb[4];
    #pragma unroll
    for (int q = 0; q < 4; q++) {
        pa[q] = *(const float4*)(ArowP + q * 4);
        pb[q] = *(const float4*)(BrowP + q * 4);
    }

    for (int i = 0; i < NC; i++) {
        // stage prefetched chunk into smem (converted to tf32)
        #pragma unroll
        for (int q = 0; q < 4; q++) {
            sAw[q*4+0] = f2tf32(pa[q].x); sAw[q*4+1] = f2tf32(pa[q].y);
            sAw[q*4+2] = f2tf32(pa[q].z); sAw[q*4+3] = f2tf32(pa[q].w);
            sBw[q*4+0] = f2tf32(pb[q].x); sBw[q*4+1] = f2tf32(pb[q].y);
            sBw[q*4+2] = f2tf32(pb[q].z); sBw[q*4+3] = f2tf32(pb[q].w);
        }
        __syncthreads();
        // issue next chunk's loads early (latency hidden by mma below)
        if (i + 1 < NC) {
            #pragma unroll
            for (int q = 0; q < 4; q++) {
                pa[q] = *(const float4*)(ArowP + (i + 1) * 32 + q * 4);
                pb[q] = *(const float4*)(BrowP + (i + 1) * 32 + q * 4);
            }
        }
        // 4 k-steps of 8
        #pragma unroll
        for (int ks = 0; ks < 4; ks++) {
            int k0 = ks * 8;
            uint32_t af[2][4], bf[8][2];
            #pragma unroll
            for (int mt = 0; mt < 2; mt++) {
                const uint32_t* base = sA + (wm * 32 + mt * 16 + gq) * SSTR + k0 + tg;
                af[mt][0] = base[0];
                af[mt][1] = base[8 * SSTR];
                af[mt][2] = base[4];
                af[mt][3] = base[8 * SSTR + 4];
            }
            #pragma unroll
            for (int nt = 0; nt < 8; nt++) {
                const uint32_t* base = sB + (wn * 64 + nt * 8 + gq) * SSTR + k0 + tg;
                bf[nt][0] = base[0];
                bf[nt][1] = base[4];
            }
            #pragma unroll
            for (int mt = 0; mt < 2; mt++)
                #pragma unroll
                for (int nt = 0; nt < 8; nt++)
                    mma1688(acc[mt][nt], af[mt], bf[nt]);
        }
        __syncthreads();
    }

    // epilogue: c0,c1 at (row, 2*tg), c2,c3 at (row+8, 2*tg)
    #pragma unroll
    for (int mt = 0; mt < 2; mt++) {
        #pragma unroll
        for (int nt = 0; nt < 8; nt++) {
            int col = blockIdx.x * 128 + wn * 64 + nt * 8 + 2 * tg;
            float2 bb = *(const float2*)(bias + col);
            #pragma unroll
            for (int h = 0; h < 2; h++) {
                int row = blockIdx.y * 128 + wm * 32 + mt * 16 + gq + h * 8;
                size_t off = (size_t)row * Mout + col;
                float2 o;
                o.x = acc[mt][nt][2 * h + 0] + bb.x;
                o.y = acc[mt][nt][2 * h + 1] + bb.y;
                if (EPI == 1) { o.x = gelu_f(o.x); o.y = gelu_f(o.y); }
                if (EPI == 2) {
                    float2 rr = *(const float2*)(res + off);
                    o.x += rr.x; o.y += rr.y;
                }
                *(float2*)(C + off) = o;
            }
        }
    }
}

// ---------------- fused flash attention (fp32, causal + pad mask) -----------
__global__ __launch_bounds__(256, 2)
void attn_k() {
    __shared__ float Qs[64][64];
    __shared__ float KP[64][64];   // K^T during S-compute, then reused for P
    __shared__ float Vs[64][64];

    int qt = blockIdx.x, bh = blockIdx.y;
    int b = bh >> 4, h = bh & 15;
    int tid = threadIdx.x;
    int ty = tid >> 4, tx = tid & 15;
    int lr = tid >> 2;
    int ld0 = (tid & 3) * 16;

    {
        size_t qb = (size_t)(b * SD + qt * 64 + lr) * DD + h * DHH + ld0;
        #pragma unroll
        for (int q = 0; q < 4; q++)
            *(float4*)&Qs[lr][ld0 + q * 4] = *(const float4*)(g_q + qb + q * 4);
    }

    float Oa[4][4];
    float m[4], l[4];
    #pragma unroll
    for (int i = 0; i < 4; i++) {
        m[i] = -1e30f; l[i] = 0.0f;
        #pragma unroll
        for (int j = 0; j < 4; j++) Oa[i][j] = 0.0f;
    }
    const float scale = 0.125f;

    for (int kb = 0; kb <= qt; kb++) {
        __syncthreads();
        {
            size_t kbse = (size_t)(b * SD + kb * 64 + lr) * DD + h * DHH + ld0;
            #pragma unroll
            for (int q = 0; q < 4; q++) {
                float4 kv = *(const float4*)(g_k + kbse + q * 4);
                KP[ld0 + q * 4 + 0][lr] = kv.x;
                KP[ld0 + q * 4 + 1][lr] = kv.y;
                KP[ld0 + q * 4 + 2][lr] = kv.z;
                KP[ld0 + q * 4 + 3][lr] = kv.w;
                *(float4*)&Vs[lr][ld0 + q * 4] = *(const float4*)(g_v + kbse + q * 4);
            }
        }
        __syncthreads();

        float sv[4][4];
        #pragma unroll
        for (int i = 0; i < 4; i++)
            #pragma unroll
            for (int j = 0; j < 4; j++) sv[i][j] = 0.0f;

        #pragma unroll
        for (int d = 0; d < 64; d += 4) {
            float kr[4][4];
            #pragma unroll
            for (int dd = 0; dd < 4; dd++) {
                float4 t = *(float4*)&KP[d + dd][tx * 4];
                kr[dd][0] = t.x; kr[dd][1] = t.y; kr[dd][2] = t.z; kr[dd][3] = t.w;
            }
            #pragma unroll
            for (int i = 0; i < 4; i++) {
                float4 q4 = *(float4*)&Qs[ty * 4 + i][d];
                float qa[4] = {q4.x, q4.y, q4.z, q4.w};
                #pragma unroll
                for (int dd = 0; dd < 4; dd++)
                    #pragma unroll
                    for (int j = 0; j < 4; j++)
                        sv[i][j] += qa[dd] * kr[dd][j];
            }
        }

        float4 pd = *(const float4*)(g_pad + (size_t)b * SD + kb * 64 + tx * 4);
        float padv[4] = {pd.x, pd.y, pd.z, pd.w};
        bool diag = (kb == qt);
        float p[4][4];
        #pragma unroll
        for (int i = 0; i < 4; i++) {
            int qrow = ty * 4 + i;
            float mx = -1e30f;
            #pragma unroll
            for (int j = 0; j < 4; j++) {
                float val = sv[i][j] * scale + padv[j];
                if (diag && (tx * 4 + j) > qrow) val += NEGV;
                sv[i][j] = val;
                mx = fmaxf(mx, val);
            }
            #pragma unroll
            for (int o = 8; o; o >>= 1)
                mx = fmaxf(mx, __shfl_xor_sync(0xffffffffu, mx, o));
            float mn = fmaxf(m[i], mx);
            float corr = __expf(m[i] - mn);
            m[i] = mn;
            float rs = 0.0f;
            #pragma unroll
            for (int j = 0; j < 4; j++) {
                p[i][j] = __expf(sv[i][j] - mn);
                rs += p[i][j];
            }
            #pragma unroll
            for (int o = 8; o; o >>= 1)
                rs += __shfl_xor_sync(0xffffffffu, rs, o);
            l[i] = l[i] * corr + rs;
            #pragma unroll
            for (int j = 0; j < 4; j++) Oa[i][j] *= corr;
        }

        __syncthreads();
        #pragma unroll
        for (int i = 0; i < 4; i++) {
            float4 o = make_float4(p[i][0], p[i][1], p[i][2], p[i][3]);
            *(float4*)&KP[ty * 4 + i][tx * 4] = o;
        }
        __syncthreads();

        #pragma unroll
        for (int k = 0; k < 64; k += 4) {
            float vr[4][4];
            #pragma unroll
            for (int kk = 0; kk < 4; kk++) {
                float4 t = *(float4*)&Vs[k + kk][tx * 4];
                vr[kk][0] = t.x; vr[kk][1] = t.y; vr[kk][2] = t.z; vr[kk][3] = t.w;
            }
            #pragma unroll
            for (int i = 0; i < 4; i++) {
                float4 pr = *(float4*)&KP[ty * 4 + i][k];
                float pa[4] = {pr.x, pr.y, pr.z, pr.w};
                #pragma unroll
                for (int kk = 0; kk < 4; kk++)
                    #pragma unroll
                    for (int j = 0; j < 4; j++)
                        Oa[i][j] += pa[kk] * vr[kk][j];
            }
        }
    }

    #pragma unroll
    for (int i = 0; i < 4; i++) {
        float inv = 1.0f / l[i];
        size_t off = (size_t)(b * SD + qt * 64 + ty * 4 + i) * DD + h * DHH + tx * 4;
        float4 o = make_float4(Oa[i][0] * inv, Oa[i][1] * inv,
                               Oa[i][2] * inv, Oa[i][3] * inv);
        *(float4*)(g_att + off) = o;
    }
}

// ---------------- launch --------------------------------------------------
extern "C" void kernel_launch(void* const* d_in, const int* in_sizes, int n_in,
                              void* d_out, int out_size) {
    const int*   tokens = (const int*)  d_in[0];
    const float* emb    = (const float*)d_in[1];
    const float* pos    = (const float*)d_in[2];
    const float* ln1_g  = (const float*)d_in[3];
    const float* ln1_b  = (const float*)d_in[4];
    const float* ln2_g  = (const float*)d_in[5];
    const float* ln2_b  = (const float*)d_in[6];
    const float* ln3_g  = (const float*)d_in[7];
    const float* ln3_b  = (const float*)d_in[8];
    const float* Wq     = (const float*)d_in[9];
    const float* bq     = (const float*)d_in[10];
    const float* Wk     = (const float*)d_in[11];
    const float* bk     = (const float*)d_in[12];
    const float* Wv     = (const float*)d_in[13];
    const float* bv     = (const float*)d_in[14];
    const float* Wo     = (const float*)d_in[15];
    const float* bo     = (const float*)d_in[16];
    const float* W1     = (const float*)d_in[17];
    const float* b1     = (const float*)d_in[18];
    const float* W2     = (const float*)d_in[19];
    const float* b2     = (const float*)d_in[20];
    float* out = (float*)d_out;

    float *xp, *qp, *kp, *vp, *attp, *aop, *xnp, *hp;
    float *wqp, *wkp, *wvp, *wop, *w1p, *w2p;
    cudaGetSymbolAddress((void**)&xp,   g_x);
    cudaGetSymbolAddress((void**)&qp,   g_q);
    cudaGetSymbolAddress((void**)&kp,   g_k);
    cudaGetSymbolAddress((void**)&vp,   g_v);
    cudaGetSymbolAddress((void**)&attp, g_att);
    cudaGetSymbolAddress((void**)&aop,  g_ao);
    cudaGetSymbolAddress((void**)&xnp,  g_xn);
    cudaGetSymbolAddress((void**)&hp,   g_h);
    cudaGetSymbolAddress((void**)&wqp,  g_wq);
    cudaGetSymbolAddress((void**)&wkp,  g_wk);
    cudaGetSymbolAddress((void**)&wvp,  g_wv);
    cudaGetSymbolAddress((void**)&wop,  g_wo);
    cudaGetSymbolAddress((void**)&w1p,  g_w1);
    cudaGetSymbolAddress((void**)&w2p,  g_w2);

    dim3 tb(32, 8);
    // 1) embedding + LN1, weight transposes
    embed_ln_k<<<NR, 256>>>(tokens, emb, pos, ln1_g, ln1_b);
    transpose_k<<<dim3(DD / 32, DD / 32),  tb>>>(Wq, wqp, DD, DD);
    transpose_k<<<dim3(DD / 32, DD / 32),  tb>>>(Wk, wkp, DD, DD);
    transpose_k<<<dim3(DD / 32, DD / 32),  tb>>>(Wv, wvp, DD, DD);
    transpose_k<<<dim3(DD / 32, DD / 32),  tb>>>(Wo, wop, DD, DD);
    transpose_k<<<dim3(FFD / 32, DD / 32), tb>>>(W1, w1p, DD, FFD);
    transpose_k<<<dim3(DD / 32, FFD / 32), tb>>>(W2, w2p, FFD, DD);

    // 2) QKV projections (mma.sync tf32)
    tc_gemm<0><<<dim3(DD / 128, NR / 128), 256>>>(xp, wqp, bq, qp, DD, DD, nullptr);
    tc_gemm<0><<<dim3(DD / 128, NR / 128), 256>>>(xp, wkp, bk, kp, DD, DD, nullptr);
    tc_gemm<0><<<dim3(DD / 128, NR / 128), 256>>>(xp, wvp, bv, vp, DD, DD, nullptr);

    // 3) fused attention
    attn_k<<<dim3(SD / 64, BD * HH), 256>>>();

    // 4) output projection + residual LN2
    tc_gemm<0><<<dim3(DD / 128, NR / 128), 256>>>(attp, wop, bo, aop, DD, DD, nullptr);
    ln_k<0><<<NR, 256>>>(aop, ln2_g, ln2_b);

    // 5) FFN
    ln_k<1><<<NR, 256>>>(xp, ln3_g, ln3_b);
    tc_gemm<1><<<dim3(FFD / 128, NR / 128), 256>>>(xnp, w1p, b1, hp, DD, FFD, nullptr);
    tc_gemm<2><<<dim3(DD / 128, NR / 128), 256>>>(hp, w2p, b2, out, FFD, DD, xp);
}

// round 4
// speedup vs baseline: 2.2061x; 1.1878x over previous
#include <cuda_runtime.h>
#include <cstdint>
#include <math.h>

#define BD   2
#define SD   2048
#define DD   1024
#define HH   16
#define DHH  64
#define FFD  4096
#define NR   (BD*SD)              // 4096 rows
#define NEGV (-1000000000.0f)

// ---------------- scratch (static device globals; no allocation allowed) ----
__device__ float g_x  [NR*DD];
__device__ float g_q  [NR*DD];
__device__ float g_k  [NR*DD];
__device__ float g_v  [NR*DD];
__device__ float g_att[NR*DD];
__device__ float g_ao [NR*DD];
__device__ float g_xn [NR*DD];
__device__ float g_h  [(size_t)NR*FFD];
__device__ float g_pad[NR];
// transposed weights [N,K] K-major
__device__ float g_wq[DD*DD];
__device__ float g_wk[DD*DD];
__device__ float g_wv[DD*DD];
__device__ float g_wo[DD*DD];
__device__ float g_w1[(size_t)DD*FFD];
__device__ float g_w2[(size_t)DD*FFD];

// ---------------- block-wide sum over 256 threads ---------------------------
__device__ __forceinline__ float blockSum(float v, float* sm) {
    int lane = threadIdx.x & 31;
    #pragma unroll
    for (int o = 16; o; o >>= 1) v += __shfl_xor_sync(0xffffffffu, v, o);
    if (lane == 0) sm[threadIdx.x >> 5] = v;
    __syncthreads();
    float t = sm[lane & 7];
    #pragma unroll
    for (int o = 4; o; o >>= 1) t += __shfl_xor_sync(0xffffffffu, t, o);
    __syncthreads();
    return t;
}

// ---------------- K1: embedding + pos + LN1 -> g_x ; pad mask ---------------
__global__ void embed_ln_k(const int* __restrict__ tok,
                           const float* __restrict__ emb,
                           const float* __restrict__ pos,
                           const float* __restrict__ gam,
                           const float* __restrict__ bet) {
    __shared__ float sm[8];
    int n = blockIdx.x;
    int t = tok[n];
    int s = n & (SD - 1);
    int c0 = threadIdx.x * 4;
    float4 e = *(const float4*)(emb + (size_t)t * DD + c0);
    float4 p = *(const float4*)(pos + (size_t)s * DD + c0);
    float v0 = e.x + p.x, v1 = e.y + p.y, v2 = e.z + p.z, v3 = e.w + p.w;
    float mean = blockSum(v0 + v1 + v2 + v3, sm) * (1.0f / DD);
    float d0 = v0 - mean, d1 = v1 - mean, d2 = v2 - mean, d3 = v3 - mean;
    float var = blockSum(d0*d0 + d1*d1 + d2*d2 + d3*d3, sm) * (1.0f / DD);
    float rs = rsqrtf(var + 1e-5f);
    float4 gg = *(const float4*)(gam + c0);
    float4 bb = *(const float4*)(bet + c0);
    float4 o;
    o.x = d0 * rs * gg.x + bb.x;
    o.y = d1 * rs * gg.y + bb.y;
    o.z = d2 * rs * gg.z + bb.z;
    o.w = d3 * rs * gg.w + bb.w;
    *(float4*)(g_x + (size_t)n * DD + c0) = o;
    if (threadIdx.x == 0) g_pad[n] = (t == 0) ? NEGV : 0.0f;
}

// ---------------- LN kernels: MODE 0: g_x += LN(in); MODE 1: g_xn = LN(in) --
template <int MODE>
__global__ void ln_k(const float* __restrict__ in,
                     const float* __restrict__ gam,
                     const float* __restrict__ bet) {
    __shared__ float sm[8];
    int n = blockIdx.x;
    int c0 = threadIdx.x * 4;
    float4 iv = *(const float4*)(in + (size_t)n * DD + c0);
    float mean = blockSum(iv.x + iv.y + iv.z + iv.w, sm) * (1.0f / DD);
    float d0 = iv.x - mean, d1 = iv.y - mean, d2 = iv.z - mean, d3 = iv.w - mean;
    float var = blockSum(d0*d0 + d1*d1 + d2*d2 + d3*d3, sm) * (1.0f / DD);
    float rs = rsqrtf(var + 1e-5f);
    float4 gg = *(const float4*)(gam + c0);
    float4 bb = *(const float4*)(bet + c0);
    float4 o;
    o.x = d0 * rs * gg.x + bb.x;
    o.y = d1 * rs * gg.y + bb.y;
    o.z = d2 * rs * gg.z + bb.z;
    o.w = d3 * rs * gg.w + bb.w;
    if (MODE == 0) {
        float4 x = *(float4*)(g_x + (size_t)n * DD + c0);
        x.x += o.x; x.y += o.y; x.z += o.z; x.w += o.w;
        *(float4*)(g_x + (size_t)n * DD + c0) = x;
    } else {
        *(float4*)(g_xn + (size_t)n * DD + c0) = o;
    }
}

// ---------------- weight transpose: out[C,R] = in[R,C]^T --------------------
__global__ void transpose_k(const float* __restrict__ in, float* __restrict__ out,
                            int R, int Cc) {
    __shared__ float t[32][33];
    int bx = blockIdx.x * 32, by = blockIdx.y * 32;
    int x = bx + threadIdx.x;
    #pragma unroll
    for (int i = 0; i < 4; i++)
        t[threadIdx.y + i * 8][threadIdx.x] = in[(size_t)(by + threadIdx.y + i * 8) * Cc + x];
    __syncthreads();
    int xo = by + threadIdx.x;
    #pragma unroll
    for (int i = 0; i < 4; i++)
        out[(size_t)(bx + threadIdx.y + i * 8) * R + xo] = t[threadIdx.x][threadIdx.y + i * 8];
}

// ---------------- tf32 mma helpers -----------------------------------------
__device__ __forceinline__ float gelu_f(float x) {
    return 0.5f * x * (1.0f + erff(x * 0.70710678118654752f));
}
__device__ __forceinline__ uint32_t f2tf32(float x) {
    uint32_t t;
    asm("cvt.rna.tf32.f32 %0, %1;" : "=r"(t) : "f"(x));
    return t;
}
__device__ __forceinline__ void mma1688(float* c, const uint32_t* a, const uint32_t* b) {
    asm volatile(
        "mma.sync.aligned.m16n8k8.row.col.f32.tf32.tf32.f32 "
        "{%0,%1,%2,%3}, {%4,%5,%6,%7}, {%8,%9}, {%0,%1,%2,%3};"
        : "+f"(c[0]), "+f"(c[1]), "+f"(c[2]), "+f"(c[3])
        : "r"(a[0]), "r"(a[1]), "r"(a[2]), "r"(a[3]), "r"(b[0]), "r"(b[1]));
}

// ---------------- mma.sync tf32 GEMM ---------------------------------------
#define SSTR 36

template <int EPI>
__global__ __launch_bounds__(256)
void tc_gemm(const float* __restrict__ A, const float* __restrict__ Bt,
             const float* __restrict__ bias, float* __restrict__ C,
             int K, int Mout, const float* __restrict__ res) {
    __shared__ uint32_t sA[128 * SSTR];
    __shared__ uint32_t sB[128 * SSTR];

    int tid  = threadIdx.x;
    int wid  = tid >> 5;
    int lane = tid & 31;
    int wm   = wid >> 1;
    int wn   = wid & 1;
    int gq   = lane >> 2;
    int tg   = lane & 3;

    int r  = tid >> 1;
    int cb = (tid & 1) * 16;
    const float* ArowP = A  + (size_t)(blockIdx.y * 128 + r) * K + cb;
    const float* BrowP = Bt + (size_t)(blockIdx.x * 128 + r) * K + cb;
    uint32_t* sAw = sA + r * SSTR + cb;
    uint32_t* sBw = sB + r * SSTR + cb;

    float acc[2][8][4];
    #pragma unroll
    for (int mt = 0; mt < 2; mt++)
        #pragma unroll
        for (int nt = 0; nt < 8; nt++)
            #pragma unroll
            for (int c = 0; c < 4; c++) acc[mt][nt][c] = 0.0f;

    int NC = K >> 5;
    float4 pa[4], pb[4];
    #pragma unroll
    for (int q = 0; q < 4; q++) {
        pa[q] = *(const float4*)(ArowP + q * 4);
        pb[q] = *(const float4*)(BrowP + q * 4);
    }

    for (int i = 0; i < NC; i++) {
        #pragma unroll
        for (int q = 0; q < 4; q++) {
            sAw[q*4+0] = f2tf32(pa[q].x); sAw[q*4+1] = f2tf32(pa[q].y);
            sAw[q*4+2] = f2tf32(pa[q].z); sAw[q*4+3] = f2tf32(pa[q].w);
            sBw[q*4+0] = f2tf32(pb[q].x); sBw[q*4+1] = f2tf32(pb[q].y);
            sBw[q*4+2] = f2tf32(pb[q].z); sBw[q*4+3] = f2tf32(pb[q].w);
        }
        __syncthreads();
        if (i + 1 < NC) {
            #pragma unroll
            for (int q = 0; q < 4; q++) {
                pa[q] = *(const float4*)(ArowP + (i + 1) * 32 + q * 4);
                pb[q] = *(const float4*)(BrowP + (i + 1) * 32 + q * 4);
            }
        }
        #pragma unroll
        for (int ks = 0; ks < 4; ks++) {
            int k0 = ks * 8;
            uint32_t af[2][4], bf[8][2];
            #pragma unroll
            for (int mt = 0; mt < 2; mt++) {
                const uint32_t* base = sA + (wm * 32 + mt * 16 + gq) * SSTR + k0 + tg;
                af[mt][0] = base[0];
                af[mt][1] = base[8 * SSTR];
                af[mt][2] = base[4];
                af[mt][3] = base[8 * SSTR + 4];
            }
            #pragma unroll
            for (int nt = 0; nt < 8; nt++) {
                const uint32_t* base = sB + (wn * 64 + nt * 8 + gq) * SSTR + k0 + tg;
                bf[nt][0] = base[0];
                bf[nt][1] = base[4];
            }
            #pragma unroll
            for (int mt = 0; mt < 2; mt++)
                #pragma unroll
                for (int nt = 0; nt < 8; nt++)
                    mma1688(acc[mt][nt], af[mt], bf[nt]);
        }
        __syncthreads();
    }

    #pragma unroll
    for (int mt = 0; mt < 2; mt++) {
        #pragma unroll
        for (int nt = 0; nt < 8; nt++) {
            int col = blockIdx.x * 128 + wn * 64 + nt * 8 + 2 * tg;
            float2 bb = *(const float2*)(bias + col);
            #pragma unroll
            for (int h = 0; h < 2; h++) {
                int row = blockIdx.y * 128 + wm * 32 + mt * 16 + gq + h * 8;
                size_t off = (size_t)row * Mout + col;
                float2 o;
                o.x = acc[mt][nt][2 * h + 0] + bb.x;
                o.y = acc[mt][nt][2 * h + 1] + bb.y;
                if (EPI == 1) { o.x = gelu_f(o.x); o.y = gelu_f(o.y); }
                if (EPI == 2) {
                    float2 rr = *(const float2*)(res + off);
                    o.x += rr.x; o.y += rr.y;
                }
                *(float2*)(C + off) = o;
            }
        }
    }
}

// ---------------- tensor-core flash attention (tf32) ------------------------
// grid (32, 32), 128 threads (4 warps). 64 queries/CTA (warp: m16), key tiles 64.
#define ASTR 68

// quad-permute a P c-fragment pair (cols 2tg,2tg+1) into a-frag cols (tg, tg+4)
__device__ __forceinline__ void quad_permute(uint32_t p0, uint32_t p1, int lane,
                                             uint32_t& a_lo, uint32_t& a_hi) {
    int tg = lane & 3;
    int base = lane & ~3;
    int l1 = base + (tg >> 1);
    int l2 = base + 2 + (tg >> 1);
    uint32_t s0a = __shfl_sync(0xffffffffu, p0, l1);
    uint32_t s1a = __shfl_sync(0xffffffffu, p1, l1);
    uint32_t s0b = __shfl_sync(0xffffffffu, p0, l2);
    uint32_t s1b = __shfl_sync(0xffffffffu, p1, l2);
    a_lo = (tg & 1) ? s1a : s0a;
    a_hi = (tg & 1) ? s1b : s0b;
}

__global__ __launch_bounds__(128)
void attn_tc() {
    __shared__ uint32_t sK[64 * ASTR];
    __shared__ uint32_t sV[64 * ASTR];
    __shared__ float sPad[64];

    int qt = blockIdx.x, bh = blockIdx.y;
    int b = bh >> 4, h = bh & 15;
    int tid = threadIdx.x;
    int w = tid >> 5, lane = tid & 31;
    int gq = lane >> 2, tg = lane & 3;
    int qabs0 = qt * 64 + w * 16;

    // Q fragments (tf32), register-resident
    uint32_t qa[8][4];
    const float* Qb = g_q + ((size_t)(b * SD) + qabs0) * DD + h * DHH;
    #pragma unroll
    for (int ks = 0; ks < 8; ks++) {
        qa[ks][0] = f2tf32(Qb[(size_t)gq * DD + ks * 8 + tg]);
        qa[ks][1] = f2tf32(Qb[(size_t)(gq + 8) * DD + ks * 8 + tg]);
        qa[ks][2] = f2tf32(Qb[(size_t)gq * DD + ks * 8 + tg + 4]);
        qa[ks][3] = f2tf32(Qb[(size_t)(gq + 8) * DD + ks * 8 + tg + 4]);
    }

    float m0 = -1e30f, m1 = -1e30f, l0 = 0.0f, l1 = 0.0f;
    float Oa[8][4];
    #pragma unroll
    for (int nt = 0; nt < 8; nt++)
        #pragma unroll
        for (int c = 0; c < 4; c++) Oa[nt][c] = 0.0f;

    int lr = tid >> 1;
    int lc = (tid & 1) * 32;

    for (int kb = 0; kb <= qt; kb++) {
        size_t gb = ((size_t)(b * SD) + kb * 64 + lr) * DD + h * DHH + lc;
        uint32_t* kRow = sK + lr * ASTR + lc;
        uint32_t* vRow = sV + lr * ASTR + lc;
        #pragma unroll
        for (int q = 0; q < 8; q++) {
            float4 kk = *(const float4*)(g_k + gb + q * 4);
            float4 vv = *(const float4*)(g_v + gb + q * 4);
            kRow[q*4+0] = f2tf32(kk.x); kRow[q*4+1] = f2tf32(kk.y);
            kRow[q*4+2] = f2tf32(kk.z); kRow[q*4+3] = f2tf32(kk.w);
            vRow[q*4+0] = f2tf32(vv.x); vRow[q*4+1] = f2tf32(vv.y);
            vRow[q*4+2] = f2tf32(vv.z); vRow[q*4+3] = f2tf32(vv.w);
        }
        if (tid < 64) sPad[tid] = g_pad[(size_t)b * SD + kb * 64 + tid];
        __syncthreads();

        if (kb * 64 <= qabs0 + 15) {               // warp-uniform predicate
            // ---- S = Q K^T ----
            float sv[8][4];
            #pragma unroll
            for (int nt = 0; nt < 8; nt++)
                #pragma unroll
                for (int c = 0; c < 4; c++) sv[nt][c] = 0.0f;
            #pragma unroll
            for (int ks = 0; ks < 8; ks++) {
                #pragma unroll
                for (int nt = 0; nt < 8; nt++) {
                    const uint32_t* kp = sK + (nt * 8 + gq) * ASTR + ks * 8 + tg;
                    uint32_t bk[2] = { kp[0], kp[4] };
                    mma1688(sv[nt], qa[ks], bk);
                }
            }
            // ---- masks + online softmax ----
            int q0 = qabs0 + gq, q1 = q0 + 8;
            float mx0 = -1e30f, mx1 = -1e30f;
            #pragma unroll
            for (int nt = 0; nt < 8; nt++) {
                int kc = kb * 64 + nt * 8 + 2 * tg;
                float pad0 = sPad[nt * 8 + 2 * tg];
                float pad1 = sPad[nt * 8 + 2 * tg + 1];
                sv[nt][0] = sv[nt][0] * 0.125f + pad0 + ((kc     > q0) ? NEGV : 0.0f);
                sv[nt][1] = sv[nt][1] * 0.125f + pad1 + ((kc + 1 > q0) ? NEGV : 0.0f);
                sv[nt][2] = sv[nt][2] * 0.125f + pad0 + ((kc     > q1) ? NEGV : 0.0f);
                sv[nt][3] = sv[nt][3] * 0.125f + pad1 + ((kc + 1 > q1) ? NEGV : 0.0f);
                mx0 = fmaxf(mx0, fmaxf(sv[nt][0], sv[nt][1]));
                mx1 = fmaxf(mx1, fmaxf(sv[nt][2], sv[nt][3]));
            }
            mx0 = fmaxf(mx0, __shfl_xor_sync(0xffffffffu, mx0, 1));
            mx0 = fmaxf(mx0, __shfl_xor_sync(0xffffffffu, mx0, 2));
            mx1 = fmaxf(mx1, __shfl_xor_sync(0xffffffffu, mx1, 1));
            mx1 = fmaxf(mx1, __shfl_xor_sync(0xffffffffu, mx1, 2));
            float mn0 = fmaxf(m0, mx0), mn1 = fmaxf(m1, mx1);
            float cr0 = __expf(m0 - mn0), cr1 = __expf(m1 - mn1);
            m0 = mn0; m1 = mn1;

            float rs0 = 0.0f, rs1 = 0.0f;
            uint32_t pfr[8][4];                    // P as a-fragments (k-tile = nt)
            #pragma unroll
            for (int nt = 0; nt < 8; nt++) {
                float p0 = __expf(sv[nt][0] - mn0);
                float p1 = __expf(sv[nt][1] - mn0);
                float p2 = __expf(sv[nt][2] - mn1);
                float p3 = __expf(sv[nt][3] - mn1);
                rs0 += p0 + p1; rs1 += p2 + p3;
                quad_permute(f2tf32(p0), f2tf32(p1), lane, pfr[nt][0], pfr[nt][2]);
                quad_permute(f2tf32(p2), f2tf32(p3), lane, pfr[nt][1], pfr[nt][3]);
            }
            rs0 += __shfl_xor_sync(0xffffffffu, rs0, 1);
            rs0 += __shfl_xor_sync(0xffffffffu, rs0, 2);
            rs1 += __shfl_xor_sync(0xffffffffu, rs1, 1);
            rs1 += __shfl_xor_sync(0xffffffffu, rs1, 2);
            l0 = l0 * cr0 + rs0;
            l1 = l1 * cr1 + rs1;
            #pragma unroll
            for (int nt = 0; nt < 8; nt++) {
                Oa[nt][0] *= cr0; Oa[nt][1] *= cr0;
                Oa[nt][2] *= cr1; Oa[nt][3] *= cr1;
            }
            // ---- O += P V ----
            #pragma unroll
            for (int ks = 0; ks < 8; ks++) {
                #pragma unroll
                for (int nt = 0; nt < 8; nt++) {
                    const uint32_t* vp = sV + (ks * 8 + tg) * ASTR + nt * 8 + gq;
                    uint32_t bv[2] = { vp[0], vp[4 * ASTR] };
                    mma1688(Oa[nt], pfr[ks], bv);
                }
            }
        }
        __syncthreads();
    }

    float inv0 = 1.0f / l0, inv1 = 1.0f / l1;
    size_t o0 = ((size_t)(b * SD) + qabs0 + gq) * DD + h * DHH + 2 * tg;
    size_t o1 = o0 + (size_t)8 * DD;
    #pragma unroll
    for (int nt = 0; nt < 8; nt++) {
        *(float2*)(g_att + o0 + nt * 8) = make_float2(Oa[nt][0] * inv0, Oa[nt][1] * inv0);
        *(float2*)(g_att + o1 + nt * 8) = make_float2(Oa[nt][2] * inv1, Oa[nt][3] * inv1);
    }
}

// ---------------- launch --------------------------------------------------
extern "C" void kernel_launch(void* const* d_in, const int* in_sizes, int n_in,
                              void* d_out, int out_size) {
    const int*   tokens = (const int*)  d_in[0];
    const float* emb    = (const float*)d_in[1];
    const float* pos    = (const float*)d_in[2];
    const float* ln1_g  = (const float*)d_in[3];
    const float* ln1_b  = (const float*)d_in[4];
    const float* ln2_g  = (const float*)d_in[5];
    const float* ln2_b  = (const float*)d_in[6];
    const float* ln3_g  = (const float*)d_in[7];
    const float* ln3_b  = (const float*)d_in[8];
    const float* Wq     = (const float*)d_in[9];
    const float* bq     = (const float*)d_in[10];
    const float* Wk     = (const float*)d_in[11];
    const float* bk     = (const float*)d_in[12];
    const float* Wv     = (const float*)d_in[13];
    const float* bv     = (const float*)d_in[14];
    const float* Wo     = (const float*)d_in[15];
    const float* bo     = (const float*)d_in[16];
    const float* W1     = (const float*)d_in[17];
    const float* b1     = (const float*)d_in[18];
    const float* W2     = (const float*)d_in[19];
    const float* b2     = (const float*)d_in[20];
    float* out = (float*)d_out;

    float *xp, *qp, *kp, *vp, *attp, *aop, *xnp, *hp;
    float *wqp, *wkp, *wvp, *wop, *w1p, *w2p;
    cudaGetSymbolAddress((void**)&xp,   g_x);
    cudaGetSymbolAddress((void**)&qp,   g_q);
    cudaGetSymbolAddress((void**)&kp,   g_k);
    cudaGetSymbolAddress((void**)&vp,   g_v);
    cudaGetSymbolAddress((void**)&attp, g_att);
    cudaGetSymbolAddress((void**)&aop,  g_ao);
    cudaGetSymbolAddress((void**)&xnp,  g_xn);
    cudaGetSymbolAddress((void**)&hp,   g_h);
    cudaGetSymbolAddress((void**)&wqp,  g_wq);
    cudaGetSymbolAddress((void**)&wkp,  g_wk);
    cudaGetSymbolAddress((void**)&wvp,  g_wv);
    cudaGetSymbolAddress((void**)&wop,  g_wo);
    cudaGetSymbolAddress((void**)&w1p,  g_w1);
    cudaGetSymbolAddress((void**)&w2p,  g_w2);

    dim3 tb(32, 8);
    embed_ln_k<<<NR, 256>>>(tokens, emb, pos, ln1_g, ln1_b);
    transpose_k<<<dim3(DD / 32, DD / 32),  tb>>>(Wq, wqp, DD, DD);
    transpose_k<<<dim3(DD / 32, DD / 32),  tb>>>(Wk, wkp, DD, DD);
    transpose_k<<<dim3(DD / 32, DD / 32),  tb>>>(Wv, wvp, DD, DD);
    transpose_k<<<dim3(DD / 32, DD / 32),  tb>>>(Wo, wop, DD, DD);
    transpose_k<<<dim3(FFD / 32, DD / 32), tb>>>(W1, w1p, DD, FFD);
    transpose_k<<<dim3(DD / 32, FFD / 32), tb>>>(W2, w2p, FFD, DD);

    tc_gemm<0><<<dim3(DD / 128, NR / 128), 256>>>(xp, wqp, bq, qp, DD, DD, nullptr);
    tc_gemm<0><<<dim3(DD / 128, NR / 128), 256>>>(xp, wkp, bk, kp, DD, DD, nullptr);
    tc_gemm<0><<<dim3(DD / 128, NR / 128), 256>>>(xp, wvp, bv, vp, DD, DD, nullptr);

    attn_tc<<<dim3(SD / 64, BD * HH), 128>>>();

    tc_gemm<0><<<dim3(DD / 128, NR / 128), 256>>>(attp, wop, bo, aop, DD, DD, nullptr);
    ln_k<0><<<NR, 256>>>(aop, ln2_g, ln2_b);

    ln_k<1><<<NR, 256>>>(xp, ln3_g, ln3_b);
    tc_gemm<1><<<dim3(FFD / 128, NR / 128), 256>>>(xnp, w1p, b1, hp, DD, FFD, nullptr);
    tc_gemm<2><<<dim3(DD / 128, NR / 128), 256>>>(hp, w2p, b2, out, FFD, DD, xp);
}